// round 2
// baseline (speedup 1.0000x reference)
#include <cuda_runtime.h>

#define N_ENTS  50000
#define N_EDGES 500000
#define N_RELS  200
#define RANK    128
#define SLOPE   0.22916666666666666f   // (1/8 + 1/3)/2

// ---------------- device scratch (allocation-free rule) ----------------
__device__ int   g_deg[N_ENTS];
__device__ int   g_rowptr[N_ENTS + 1];
__device__ int   g_cursor[N_ENTS];
__device__ int   g_colsrc[N_EDGES];
__device__ int   g_colet[N_EDGES];
__device__ float g_relagg[(size_t)N_ENTS * RANK];
__device__ float g_aggn[(size_t)N_ENTS * RANK];
__device__ float g_h1[(size_t)N_ENTS * RANK];
__device__ int   g_deg0_list[N_ENTS];
__device__ int   g_deg0_count;

// ---------------- small helpers ----------------
__device__ __forceinline__ unsigned long long dupf(float a) {
    unsigned long long r;
    asm("mov.b64 %0, {%1, %1};" : "=l"(r) : "f"(a));
    return r;
}
__device__ __forceinline__ void ffma2(unsigned long long& c, unsigned long long a,
                                      unsigned long long b) {
    asm("fma.rn.f32x2 %0, %1, %2, %0;" : "+l"(c) : "l"(a), "l"(b));
}

// ---------------- CSR build ----------------
__global__ void init_kernel() {
    int i = blockIdx.x * blockDim.x + threadIdx.x;
    if (i < N_ENTS) g_deg[i] = 0;
    if (i == 0) g_deg0_count = 0;
}

__global__ void hist_kernel(const int* __restrict__ dst) {
    int e = blockIdx.x * blockDim.x + threadIdx.x;
    if (e < N_EDGES) atomicAdd(&g_deg[dst[e]], 1);
}

// single block, 1024 threads: exclusive scan of degrees -> rowptr/cursor,
// collect deg-0 nodes.
__global__ void scan_kernel() {
    __shared__ int sums[1024];
    const int CH = 49;  // 1024*49 >= 50000
    int t = threadIdx.x;
    int start = t * CH;
    int end = start + CH; if (end > N_ENTS) end = N_ENTS;
    int s = 0;
    for (int i = start; i < end; i++) s += g_deg[i];
    sums[t] = s;
    __syncthreads();
    for (int off = 1; off < 1024; off <<= 1) {
        int v = (t >= off) ? sums[t - off] : 0;
        __syncthreads();
        sums[t] += v;
        __syncthreads();
    }
    int run = sums[t] - s;  // exclusive prefix
    for (int i = start; i < end; i++) {
        g_rowptr[i] = run;
        g_cursor[i] = run;
        int d = g_deg[i];
        if (d == 0) {
            int p = atomicAdd(&g_deg0_count, 1);
            g_deg0_list[p] = i;
        }
        run += d;
    }
    if (t == 1023) g_rowptr[N_ENTS] = sums[1023];
}

__global__ void fill_kernel(const int* __restrict__ src, const int* __restrict__ dst,
                            const int* __restrict__ et) {
    int e = blockIdx.x * blockDim.x + threadIdx.x;
    if (e < N_EDGES) {
        int d = dst[e];
        int p = atomicAdd(&g_cursor[d], 1);
        g_colsrc[p] = src[e];
        g_colet[p]  = et[e];
    }
}

// per-dst sum of rel_emb[etype] (constant across layers)
__global__ void relagg_kernel(const float* __restrict__ rel) {
    int w = (blockIdx.x * blockDim.x + threadIdx.x) >> 5;
    if (w >= N_ENTS) return;
    int lane = threadIdx.x & 31;
    int e0 = g_rowptr[w], e1 = g_rowptr[w + 1];
    float4 acc = make_float4(0.f, 0.f, 0.f, 0.f);
    for (int base = e0; base < e1; base += 32) {
        int my = 0;
        if (base + lane < e1) my = g_colet[base + lane];
        int cnt = e1 - base; if (cnt > 32) cnt = 32;
        for (int j = 0; j < cnt; j++) {
            int etp = __shfl_sync(0xffffffffu, my, j);
            float4 r = reinterpret_cast<const float4*>(rel + (size_t)etp * RANK)[lane];
            acc.x += r.x; acc.y += r.y; acc.z += r.z; acc.w += r.w;
        }
    }
    reinterpret_cast<float4*>(g_relagg + (size_t)w * RANK)[lane] = acc;
}

// aggn[v] = norm[v] * (relagg[v] + sum_{e into v} h[src[e]])
__global__ void agg_kernel(const float* __restrict__ h_ext,
                           const float* __restrict__ norm) {
    const float* __restrict__ h = h_ext ? h_ext : (const float*)g_h1;
    int w = (blockIdx.x * blockDim.x + threadIdx.x) >> 5;
    if (w >= N_ENTS) return;
    int lane = threadIdx.x & 31;
    int e0 = g_rowptr[w], e1 = g_rowptr[w + 1];
    float4 acc = reinterpret_cast<const float4*>(g_relagg + (size_t)w * RANK)[lane];
    for (int base = e0; base < e1; base += 32) {
        int my = 0;
        if (base + lane < e1) my = g_colsrc[base + lane];
        int cnt = e1 - base; if (cnt > 32) cnt = 32;
        for (int j = 0; j < cnt; j++) {
            int s = __shfl_sync(0xffffffffu, my, j);
            float4 r = reinterpret_cast<const float4*>(h + (size_t)s * RANK)[lane];
            acc.x += r.x; acc.y += r.y; acc.z += r.z; acc.w += r.w;
        }
    }
    float nm = norm[w];
    acc.x *= nm; acc.y *= nm; acc.z *= nm; acc.w *= nm;
    reinterpret_cast<float4*>(g_aggn + (size_t)w * RANK)[lane] = acc;
}

// Out = leaky( aggn @ Wn + h @ Wl ), fused K=256 GEMM with f32x2 packed FMA.
// BM=128, BN=128, BK=8, 256 threads, 8x8 micro-tile per thread.
__global__ void __launch_bounds__(256, 2)
gemm_kernel(const float* __restrict__ A1_ext,  // h; null -> g_h1
            const float* __restrict__ B0,      // Wn[l]
            const float* __restrict__ B1,      // Wl[l]
            float* __restrict__ out_ext)       // null -> g_h1
{
    const float* __restrict__ A0 = (const float*)g_aggn;
    const float* __restrict__ A1 = A1_ext ? A1_ext : (const float*)g_h1;
    float* __restrict__ Out = out_ext ? out_ext : (float*)g_h1;

    __shared__ float As[8][132];   // [k][m], padded stride (16B-aligned, conflict-free)
    __shared__ float Bs[8][128];   // [k][n]

    const int tid = threadIdx.x;
    const int block_row = blockIdx.x * 128;
    const int tx = tid & 15;       // col group: cols tx*8 .. +7
    const int ty = tid >> 4;       // row group: rows ty*8 .. +7

    unsigned long long c[8][4];
#pragma unroll
    for (int i = 0; i < 8; i++)
#pragma unroll
        for (int j = 0; j < 4; j++) c[i][j] = 0ULL;

    const int a_row  = tid >> 1;
    const int a_part = (tid & 1) * 4;
    const int b_krow = tid >> 5;
    const int b_col  = (tid & 31) * 4;
    const int grow_a = block_row + a_row;

    for (int kt = 0; kt < 32; kt++) {
        const float* Asrc = (kt < 16) ? A0 : A1;
        const float* Bsrc = (kt < 16) ? B0 : B1;
        const int kk = (kt & 15) * 8;

        float4 av = make_float4(0.f, 0.f, 0.f, 0.f);
        if (grow_a < N_ENTS)
            av = *reinterpret_cast<const float4*>(Asrc + (size_t)grow_a * RANK + kk + a_part);
        float4 bv = *reinterpret_cast<const float4*>(Bsrc + (size_t)(kk + b_krow) * RANK + b_col);

        __syncthreads();
        As[a_part + 0][a_row] = av.x;
        As[a_part + 1][a_row] = av.y;
        As[a_part + 2][a_row] = av.z;
        As[a_part + 3][a_row] = av.w;
        *reinterpret_cast<float4*>(&Bs[b_krow][b_col]) = bv;
        __syncthreads();

#pragma unroll
        for (int k2 = 0; k2 < 8; k2++) {
            float4 a0 = *reinterpret_cast<const float4*>(&As[k2][ty * 8]);
            float4 a1 = *reinterpret_cast<const float4*>(&As[k2][ty * 8 + 4]);
            const unsigned long long* bp =
                reinterpret_cast<const unsigned long long*>(&Bs[k2][tx * 8]);
            unsigned long long b0 = bp[0], b1 = bp[1], b2 = bp[2], b3 = bp[3];
            float a[8] = {a0.x, a0.y, a0.z, a0.w, a1.x, a1.y, a1.z, a1.w};
#pragma unroll
            for (int i = 0; i < 8; i++) {
                unsigned long long aa = dupf(a[i]);
                ffma2(c[i][0], aa, b0);
                ffma2(c[i][1], aa, b1);
                ffma2(c[i][2], aa, b2);
                ffma2(c[i][3], aa, b3);
            }
        }
    }

#pragma unroll
    for (int i = 0; i < 8; i++) {
        int grow = block_row + ty * 8 + i;
        if (grow >= N_ENTS) continue;
        float o[8];
#pragma unroll
        for (int j = 0; j < 4; j++) {
            float2 p = *reinterpret_cast<float2*>(&c[i][j]);
            o[2 * j] = p.x; o[2 * j + 1] = p.y;
        }
#pragma unroll
        for (int j = 0; j < 8; j++) o[j] = (o[j] >= 0.f) ? o[j] : o[j] * SLOPE;
        float* dstp = Out + (size_t)grow * RANK + tx * 8;
        *reinterpret_cast<float4*>(dstp)     = make_float4(o[0], o[1], o[2], o[3]);
        *reinterpret_cast<float4*>(dstp + 4) = make_float4(o[4], o[5], o[6], o[7]);
    }
}

// deg-0 nodes use Wa instead of Wl (and have zero agg): overwrite.
__global__ void fixup_kernel(const float* __restrict__ h_ext,
                             const float* __restrict__ Wa,
                             float* __restrict__ out_ext) {
    const float* __restrict__ h = h_ext ? h_ext : (const float*)g_h1;
    float* __restrict__ Out = out_ext ? out_ext : (float*)g_h1;
    int wg = (blockIdx.x * blockDim.x + threadIdx.x) >> 5;
    int lane = threadIdx.x & 31;
    int nwarp = (gridDim.x * blockDim.x) >> 5;
    int cnt = g_deg0_count;
    for (int idx = wg; idx < cnt; idx += nwarp) {
        int v = g_deg0_list[idx];
        const float* hr = h + (size_t)v * RANK;
        float4 acc = make_float4(0.f, 0.f, 0.f, 0.f);
        for (int k = 0; k < RANK; k++) {
            float a = hr[k];
            float4 wv = reinterpret_cast<const float4*>(Wa + (size_t)k * RANK)[lane];
            acc.x += a * wv.x; acc.y += a * wv.y; acc.z += a * wv.z; acc.w += a * wv.w;
        }
        acc.x = (acc.x >= 0.f) ? acc.x : acc.x * SLOPE;
        acc.y = (acc.y >= 0.f) ? acc.y : acc.y * SLOPE;
        acc.z = (acc.z >= 0.f) ? acc.z : acc.z * SLOPE;
        acc.w = (acc.w >= 0.f) ? acc.w : acc.w * SLOPE;
        reinterpret_cast<float4*>(Out + (size_t)v * RANK)[lane] = acc;
    }
}

// ---------------- launch ----------------
extern "C" void kernel_launch(void* const* d_in, const int* in_sizes, int n_in,
                              void* d_out, int out_size) {
    const float* ent  = (const float*)d_in[0];
    const float* rel  = (const float*)d_in[1];
    const float* norm = (const float*)d_in[2];
    const float* Wn   = (const float*)d_in[3];
    const float* Wl   = (const float*)d_in[4];
    const float* Wa   = (const float*)d_in[5];
    const int*   src  = (const int*)d_in[6];
    const int*   dst  = (const int*)d_in[7];
    const int*   et   = (const int*)d_in[8];
    float* out = (float*)d_out;

    const int NB  = (N_ENTS + 255) / 256;
    const int EB  = (N_EDGES + 255) / 256;
    const int AGB = (N_ENTS * 32 + 255) / 256;   // warp-per-node
    const int GB  = (N_ENTS + 127) / 128;

    init_kernel<<<NB, 256>>>();
    hist_kernel<<<EB, 256>>>(dst);
    scan_kernel<<<1, 1024>>>();
    fill_kernel<<<EB, 256>>>(src, dst, et);
    relagg_kernel<<<AGB, 256>>>(rel);

    const int WSTRIDE = RANK * RANK;  // 16384

    // layer 0: h_in = ent_emb, h_out = g_h1
    agg_kernel<<<AGB, 256>>>(ent, norm);
    gemm_kernel<<<GB, 256>>>(ent, Wn + 0 * WSTRIDE, Wl + 0 * WSTRIDE, nullptr);
    fixup_kernel<<<8, 256>>>(ent, Wa + 0 * WSTRIDE, nullptr);

    // layer 1: h_in = g_h1, h_out = d_out
    agg_kernel<<<AGB, 256>>>(nullptr, norm);
    gemm_kernel<<<GB, 256>>>(nullptr, Wn + 1 * WSTRIDE, Wl + 1 * WSTRIDE, out);
    fixup_kernel<<<8, 256>>>(nullptr, Wa + 1 * WSTRIDE, out);
}